// round 1
// baseline (speedup 1.0000x reference)
#include <cuda_runtime.h>
#include <math.h>

// ---------------- problem constants ----------------
#define BATCH   32
#define TIME    64000
#define NF      40
#define NG      4
#define NFG     10          // filters per group
#define OUT_T   400
#define PSZ     401         // POOL_SIZE
#define PSTR    160         // POOL_STRIDE
#define KMAX    512         // supported max gabor kernel length (actual <= 451)
#define CSMAX   40          // supported max conv stride (actual ~10)

// conv kernel tiling
#define TT          128     // time points per block
#define TREG        4       // time points per thread
#define CONV_THREADS 160    // 5 filter-pairs x 32 time slots
#define STAGE_STRIDE 133
#define STAGE_FLOATS 1332   // >= 10*133, even (for float2 alignment after)

// pool kernel tiling
#define POOL_J      16
#define POOL_THREADS 320

// ---------------- device scratch ----------------
__device__ float  g_o[(size_t)NG * BATCH * NFG * TIME];   // 327.7 MB squared-modulus conv out
__device__ float2 g_kern[NG * KMAX * NFG];                // gabor taps {cos, sin}
__device__ float  g_win[NG * PSZ * NFG];                  // pooling windows
__device__ int    g_meta[NG][8];                          // cs, k, ws, ps, L1

// ---------------- meta (exact replica of reference numpy logic) ----------------
__device__ __forceinline__ float clip_cf(float v) {
    return fminf(fmaxf(v, 0.0f), 3.14159265358979f);  // rounds to f32(pi)
}
__device__ __forceinline__ float clip_bw(float v) {
    const double Zd = sqrt(1.3862943611198906) / 3.141592653589793; // sqrt(2 ln2)/pi
    return fminf(fmaxf(v, (float)(2.0 * Zd)), (float)(401.0 * Zd));
}
__device__ __forceinline__ float clip_pw(float v) {
    return fminf(fmaxf(v, (float)(2.0 / 401.0)), 0.5f);
}

__device__ __forceinline__ void compute_meta(const float* cf, const float* bw, int g,
                                             int& cs, int& k, int& ws, int& ps, int& L1) {
    float cfmax = -1e30f, bwmax = -1e30f;
#pragma unroll
    for (int f = 0; f < NFG; f++) {
        cfmax = fmaxf(cfmax, clip_cf(cf[g * NFG + f]));
        bwmax = fmaxf(bwmax, clip_bw(bw[g * NFG + f]));
    }
    double s = 3.141592653589793 / (double)cfmax;   // STRIDE_FACTOR = 1
    if (s < 1.0) s = 1.0;
    const int divs[12] = {160, 80, 40, 32, 20, 16, 10, 8, 5, 4, 2, 1};
    cs = 1;
#pragma unroll
    for (int i = 0; i < 12; i++) {
        if ((double)divs[i] <= s) { cs = divs[i]; break; }
    }
    k = (int)((double)bwmax * 3.0);     // truncation like python int()
    if ((k & 1) == 0) k += 1;
    ws = (int)(401.0 / (double)cs + 0.5);
    if ((ws & 1) == 0) ws += 1;
    ps = PSTR / cs;
    L1 = (TIME - 1) / cs + 1;
}

// ---------------- prep: meta + gabor taps + pool windows ----------------
__global__ void prep_kernel(const float* __restrict__ cf, const float* __restrict__ bw,
                            const float* __restrict__ pw) {
    int g = blockIdx.x;
    int tid = threadIdx.x;
    int cs, k, ws, ps, L1;
    compute_meta(cf, bw, g, cs, k, ws, ps, L1);
    if (tid == 0) {
        g_meta[g][0] = cs; g_meta[g][1] = k; g_meta[g][2] = ws;
        g_meta[g][3] = ps; g_meta[g][4] = L1;
    }
    int k2 = k >> 1;
    // gabor taps: norm * {cos,sin}(u'*cf) * exp(-u'^2/(2 bw^2)),  norm = 1/(sqrt(2pi) bw)
    for (int i = tid; i < k * NFG; i += blockDim.x) {
        int u = i / NFG, f = i % NFG;
        float cff = clip_cf(cf[g * NFG + f]);
        float bwf = clip_bw(bw[g * NFG + f]);
        float up = (float)(u - k2);
        float gauss = expf(-(up * up) / (2.0f * bwf * bwf));
        float norm = 1.0f / (sqrtf(2.0f * 3.14159274f) * bwf);
        float sp, cp;
        sincosf(up * cff, &sp, &cp);
        g_kern[g * KMAX * NFG + i] = make_float2(norm * cp * gauss, norm * sp * gauss);
    }
    // pooling windows: exp(-0.5 * ((w - 0.5(ws-1)) / (sigma * 0.5(ws-1)))^2)
    for (int i = tid; i < ws * NFG; i += blockDim.x) {
        int w = i / NFG, f = i % NFG;
        float pwf = clip_pw(pw[g * NFG + f]);
        float sigma = pwf / (float)cs * 401.0f / (float)ws;
        float c = ((float)w - 0.5f * (float)(ws - 1)) / (sigma * 0.5f * (float)(ws - 1));
        g_win[g * PSZ * NFG + i] = expf(-0.5f * c * c);
    }
}

// ---------------- phase 1: gabor conv + squared modulus ----------------
// block: one (g, n, 128-t tile). thread = (filter-pair fg in 0..4, time-slot ts in 0..31),
// each thread accumulates 2 filters x 4 time points (C,S each) -> 16 acc regs.
extern "C" __global__ void __launch_bounds__(CONV_THREADS)
conv_kernel(const float* __restrict__ x) {
    extern __shared__ float smem[];
    int g = blockIdx.z, n = blockIdx.y;
    int cs = g_meta[g][0], k = g_meta[g][1], L1 = g_meta[g][4];
    int t0 = blockIdx.x * TT;
    if (t0 >= L1) return;
    int k2 = k >> 1;

    float* stage = smem;                                   // STAGE_FLOATS
    float2* kern = (float2*)(smem + STAGE_FLOATS);         // k*NFG float2
    float* xs = smem + STAGE_FLOATS + 2 * k * NFG;         // (TT-1)*cs + k floats
    int tid = threadIdx.x;

    // load taps (contiguous) and x tile (zero-padded)
    for (int i = tid; i < k * NFG; i += CONV_THREADS)
        kern[i] = g_kern[g * KMAX * NFG + i];
    long xlo = (long)t0 * cs - k2;
    int xcount = (TT - 1) * cs + k;
    const float* xn = x + (size_t)n * TIME;
    for (int i = tid; i < xcount; i += CONV_THREADS) {
        long xg = xlo + i;
        xs[i] = (xg >= 0 && xg < TIME) ? xn[xg] : 0.0f;
    }
    __syncthreads();

    int fg = tid % 5;
    int ts = tid / 5;          // 0..31
    int f0 = 2 * fg;

    float C0[TREG], S0[TREG], C1[TREG], S1[TREG];
#pragma unroll
    for (int r = 0; r < TREG; r++) { C0[r] = S0[r] = C1[r] = S1[r] = 0.0f; }

    const float* xbase = xs + ts * cs;
    int step = 32 * cs;
#pragma unroll 4
    for (int u = 0; u < k; u++) {
        float2 k0 = kern[u * NFG + f0];
        float2 k1 = kern[u * NFG + f0 + 1];
#pragma unroll
        for (int r = 0; r < TREG; r++) {
            float xv = xbase[r * step + u];
            C0[r] = fmaf(k0.x, xv, C0[r]);
            S0[r] = fmaf(k0.y, xv, S0[r]);
            C1[r] = fmaf(k1.x, xv, C1[r]);
            S1[r] = fmaf(k1.y, xv, S1[r]);
        }
    }

    // stage |.|^2 into smem, then coalesced store
#pragma unroll
    for (int r = 0; r < TREG; r++) {
        int tl = ts + 32 * r;
        stage[f0 * STAGE_STRIDE + tl]       = C0[r] * C0[r] + S0[r] * S0[r];
        stage[(f0 + 1) * STAGE_STRIDE + tl] = C1[r] * C1[r] + S1[r] * S1[r];
    }
    __syncthreads();
    float* obase = g_o + (size_t)(g * BATCH + n) * NFG * TIME;
    for (int i = tid; i < NFG * TT; i += CONV_THREADS) {
        int f = i >> 7, tl = i & (TT - 1);
        int t = t0 + tl;
        if (t < L1) obase[(size_t)f * TIME + t] = stage[f * STAGE_STRIDE + tl];
    }
}

// ---------------- phase 2: gaussian pooling ----------------
// block: one (g, n, 16-frame tile). smem: win[ws][10] + o tile [10][tc] (coalesced load).
extern "C" __global__ void __launch_bounds__(POOL_THREADS)
pool_kernel(float* __restrict__ out) {
    extern __shared__ float smem[];
    int g = blockIdx.z, n = blockIdx.y;
    int cs = g_meta[g][0]; (void)cs;
    int ws = g_meta[g][2], ps = g_meta[g][3], L1 = g_meta[g][4];
    int ws2 = ws >> 1;
    int j0 = blockIdx.x * POOL_J;
    int tc = (POOL_J - 1) * ps + ws;
    int stride = tc + 1;

    float* win = smem;             // ws*NFG
    float* os = smem + ws * NFG;   // NFG*stride
    int tid = threadIdx.x;

    for (int i = tid; i < ws * NFG; i += POOL_THREADS)
        win[i] = g_win[g * PSZ * NFG + i];

    int tbase = j0 * ps - ws2;
    const float* obase = g_o + (size_t)(g * BATCH + n) * NFG * TIME;
    for (int i = tid; i < NFG * tc; i += POOL_THREADS) {
        int f = i / tc, tl = i - f * tc;
        int t = tbase + tl;
        os[f * stride + tl] = (t >= 0 && t < L1) ? obase[(size_t)f * TIME + t] : 0.0f;
    }
    __syncthreads();

    int f = tid % NFG, js = tid / NFG;
    if (js < POOL_J) {
        const float* osr = os + f * stride + js * ps;
        float acc = 0.0f;
#pragma unroll 4
        for (int w = 0; w < ws; w++)
            acc = fmaf(win[w * NFG + f], osr[w], acc);
        out[((size_t)n * OUT_T + (j0 + js)) * NF + g * NFG + f] = acc;
    }
}

// ---------------- launch ----------------
extern "C" void kernel_launch(void* const* d_in, const int* in_sizes, int n_in,
                              void* d_out, int out_size) {
    const float* x  = (const float*)d_in[0];
    const float* cf = (const float*)d_in[1];
    const float* bw = (const float*)d_in[2];
    const float* pw = (const float*)d_in[3];
    float* out = (float*)d_out;

    // dynamic smem sizes (worst-case over supported meta ranges)
    const int conv_smem = (STAGE_FLOATS + 2 * KMAX * NFG + (TT - 1) * CSMAX + KMAX) * 4; // ~92 KB
    const int pool_smem = (PSZ * NFG + NFG * ((POOL_J - 1) * PSTR + PSZ + 1)) * 4;       // ~125 KB

    static int configured = 0;
    if (!configured) {
        cudaFuncSetAttribute(conv_kernel, cudaFuncAttributeMaxDynamicSharedMemorySize, conv_smem);
        cudaFuncSetAttribute(pool_kernel, cudaFuncAttributeMaxDynamicSharedMemorySize, pool_smem);
        configured = 1;
    }

    prep_kernel<<<NG, 256>>>(cf, bw, pw);

    dim3 cgrid((TIME + TT - 1) / TT, BATCH, NG);   // 500 x 32 x 4, early-exit past L1
    conv_kernel<<<cgrid, CONV_THREADS, conv_smem>>>(x);

    dim3 pgrid(OUT_T / POOL_J, BATCH, NG);          // 25 x 32 x 4
    pool_kernel<<<pgrid, POOL_THREADS, pool_smem>>>(out);
}

// round 2
// speedup vs baseline: 1.0017x; 1.0017x over previous
#include <cuda_runtime.h>
#include <math.h>

// ---------------- problem constants ----------------
#define BATCH   32
#define TIME    64000
#define NF      40
#define NG      4
#define NFG     10          // filters per group
#define OUT_T   400
#define PSZ     401         // POOL_SIZE
#define PSTR    160         // POOL_STRIDE
#define KMAX    512         // supported max gabor kernel length (actual <= 451)
#define CSMAX   40          // supported max conv stride (actual ~10)

// conv kernel tiling
#define TT          128     // time points per block
#define TREG        4       // time points per thread
#define CONV_THREADS 160    // 5 filter-pairs x 32 time slots
#define STAGE_STRIDE 133
#define STAGE_FLOATS 1332   // >= 10*133, even (for float2 alignment after)

// pool kernel tiling
#define POOL_J      16
#define POOL_THREADS 320

// ---------------- device scratch ----------------
__device__ float  g_o[(size_t)NG * BATCH * NFG * TIME];   // 327.7 MB squared-modulus conv out
__device__ float2 g_kern[NG * KMAX * NFG];                // gabor taps {cos, sin}
__device__ float  g_win[NG * PSZ * NFG];                  // pooling windows
__device__ int    g_meta[NG][8];                          // cs, k, ws, ps, L1

// ---------------- meta (exact replica of reference numpy logic) ----------------
__device__ __forceinline__ float clip_cf(float v) {
    return fminf(fmaxf(v, 0.0f), 3.14159265358979f);  // rounds to f32(pi)
}
__device__ __forceinline__ float clip_bw(float v) {
    const double Zd = sqrt(1.3862943611198906) / 3.141592653589793; // sqrt(2 ln2)/pi
    return fminf(fmaxf(v, (float)(2.0 * Zd)), (float)(401.0 * Zd));
}
__device__ __forceinline__ float clip_pw(float v) {
    return fminf(fmaxf(v, (float)(2.0 / 401.0)), 0.5f);
}

__device__ __forceinline__ void compute_meta(const float* cf, const float* bw, int g,
                                             int& cs, int& k, int& ws, int& ps, int& L1) {
    float cfmax = -1e30f, bwmax = -1e30f;
#pragma unroll
    for (int f = 0; f < NFG; f++) {
        cfmax = fmaxf(cfmax, clip_cf(cf[g * NFG + f]));
        bwmax = fmaxf(bwmax, clip_bw(bw[g * NFG + f]));
    }
    double s = 3.141592653589793 / (double)cfmax;   // STRIDE_FACTOR = 1
    if (s < 1.0) s = 1.0;
    const int divs[12] = {160, 80, 40, 32, 20, 16, 10, 8, 5, 4, 2, 1};
    cs = 1;
#pragma unroll
    for (int i = 0; i < 12; i++) {
        if ((double)divs[i] <= s) { cs = divs[i]; break; }
    }
    k = (int)((double)bwmax * 3.0);     // truncation like python int()
    if ((k & 1) == 0) k += 1;
    ws = (int)(401.0 / (double)cs + 0.5);
    if ((ws & 1) == 0) ws += 1;
    ps = PSTR / cs;
    L1 = (TIME - 1) / cs + 1;
}

// ---------------- prep: meta + gabor taps + pool windows ----------------
__global__ void prep_kernel(const float* __restrict__ cf, const float* __restrict__ bw,
                            const float* __restrict__ pw) {
    int g = blockIdx.x;
    int tid = threadIdx.x;
    int cs, k, ws, ps, L1;
    compute_meta(cf, bw, g, cs, k, ws, ps, L1);
    if (tid == 0) {
        g_meta[g][0] = cs; g_meta[g][1] = k; g_meta[g][2] = ws;
        g_meta[g][3] = ps; g_meta[g][4] = L1;
    }
    int k2 = k >> 1;
    // gabor taps: norm * {cos,sin}(u'*cf) * exp(-u'^2/(2 bw^2)),  norm = 1/(sqrt(2pi) bw)
    for (int i = tid; i < k * NFG; i += blockDim.x) {
        int u = i / NFG, f = i % NFG;
        float cff = clip_cf(cf[g * NFG + f]);
        float bwf = clip_bw(bw[g * NFG + f]);
        float up = (float)(u - k2);
        float gauss = expf(-(up * up) / (2.0f * bwf * bwf));
        float norm = 1.0f / (sqrtf(2.0f * 3.14159274f) * bwf);
        float sp, cp;
        sincosf(up * cff, &sp, &cp);
        g_kern[g * KMAX * NFG + i] = make_float2(norm * cp * gauss, norm * sp * gauss);
    }
    // pooling windows: exp(-0.5 * ((w - 0.5(ws-1)) / (sigma * 0.5(ws-1)))^2)
    for (int i = tid; i < ws * NFG; i += blockDim.x) {
        int w = i / NFG, f = i % NFG;
        float pwf = clip_pw(pw[g * NFG + f]);
        float sigma = pwf / (float)cs * 401.0f / (float)ws;
        float c = ((float)w - 0.5f * (float)(ws - 1)) / (sigma * 0.5f * (float)(ws - 1));
        g_win[g * PSZ * NFG + i] = expf(-0.5f * c * c);
    }
}

// ---------------- phase 1: gabor conv + squared modulus ----------------
// block: one (g, n, 128-t tile). thread = (filter-pair fg in 0..4, time-slot ts in 0..31),
// each thread accumulates 2 filters x 4 time points (C,S each) -> 16 acc regs.
extern "C" __global__ void __launch_bounds__(CONV_THREADS)
conv_kernel(const float* __restrict__ x) {
    extern __shared__ float smem[];
    int g = blockIdx.z, n = blockIdx.y;
    int cs = g_meta[g][0], k = g_meta[g][1], L1 = g_meta[g][4];
    int t0 = blockIdx.x * TT;
    if (t0 >= L1) return;
    int k2 = k >> 1;

    float* stage = smem;                                   // STAGE_FLOATS
    float2* kern = (float2*)(smem + STAGE_FLOATS);         // k*NFG float2
    float* xs = smem + STAGE_FLOATS + 2 * k * NFG;         // (TT-1)*cs + k floats
    int tid = threadIdx.x;

    // load taps (contiguous) and x tile (zero-padded)
    for (int i = tid; i < k * NFG; i += CONV_THREADS)
        kern[i] = g_kern[g * KMAX * NFG + i];
    long xlo = (long)t0 * cs - k2;
    int xcount = (TT - 1) * cs + k;
    const float* xn = x + (size_t)n * TIME;
    for (int i = tid; i < xcount; i += CONV_THREADS) {
        long xg = xlo + i;
        xs[i] = (xg >= 0 && xg < TIME) ? xn[xg] : 0.0f;
    }
    __syncthreads();

    int fg = tid % 5;
    int ts = tid / 5;          // 0..31
    int f0 = 2 * fg;

    float C0[TREG], S0[TREG], C1[TREG], S1[TREG];
#pragma unroll
    for (int r = 0; r < TREG; r++) { C0[r] = S0[r] = C1[r] = S1[r] = 0.0f; }

    const float* xbase = xs + ts * cs;
    int step = 32 * cs;
#pragma unroll 4
    for (int u = 0; u < k; u++) {
        float2 k0 = kern[u * NFG + f0];
        float2 k1 = kern[u * NFG + f0 + 1];
#pragma unroll
        for (int r = 0; r < TREG; r++) {
            float xv = xbase[r * step + u];
            C0[r] = fmaf(k0.x, xv, C0[r]);
            S0[r] = fmaf(k0.y, xv, S0[r]);
            C1[r] = fmaf(k1.x, xv, C1[r]);
            S1[r] = fmaf(k1.y, xv, S1[r]);
        }
    }

    // stage |.|^2 into smem, then coalesced store
#pragma unroll
    for (int r = 0; r < TREG; r++) {
        int tl = ts + 32 * r;
        stage[f0 * STAGE_STRIDE + tl]       = C0[r] * C0[r] + S0[r] * S0[r];
        stage[(f0 + 1) * STAGE_STRIDE + tl] = C1[r] * C1[r] + S1[r] * S1[r];
    }
    __syncthreads();
    float* obase = g_o + (size_t)(g * BATCH + n) * NFG * TIME;
    for (int i = tid; i < NFG * TT; i += CONV_THREADS) {
        int f = i >> 7, tl = i & (TT - 1);
        int t = t0 + tl;
        if (t < L1) obase[(size_t)f * TIME + t] = stage[f * STAGE_STRIDE + tl];
    }
}

// ---------------- phase 2: gaussian pooling ----------------
// block: one (g, n, 16-frame tile). smem: win[ws][10] + o tile [10][tc] (coalesced load).
extern "C" __global__ void __launch_bounds__(POOL_THREADS)
pool_kernel(float* __restrict__ out) {
    extern __shared__ float smem[];
    int g = blockIdx.z, n = blockIdx.y;
    int cs = g_meta[g][0]; (void)cs;
    int ws = g_meta[g][2], ps = g_meta[g][3], L1 = g_meta[g][4];
    int ws2 = ws >> 1;
    int j0 = blockIdx.x * POOL_J;
    int tc = (POOL_J - 1) * ps + ws;
    int stride = tc + 1;

    float* win = smem;             // ws*NFG
    float* os = smem + ws * NFG;   // NFG*stride
    int tid = threadIdx.x;

    for (int i = tid; i < ws * NFG; i += POOL_THREADS)
        win[i] = g_win[g * PSZ * NFG + i];

    int tbase = j0 * ps - ws2;
    const float* obase = g_o + (size_t)(g * BATCH + n) * NFG * TIME;
    for (int i = tid; i < NFG * tc; i += POOL_THREADS) {
        int f = i / tc, tl = i - f * tc;
        int t = tbase + tl;
        os[f * stride + tl] = (t >= 0 && t < L1) ? obase[(size_t)f * TIME + t] : 0.0f;
    }
    __syncthreads();

    int f = tid % NFG, js = tid / NFG;
    if (js < POOL_J) {
        const float* osr = os + f * stride + js * ps;
        float acc = 0.0f;
#pragma unroll 4
        for (int w = 0; w < ws; w++)
            acc = fmaf(win[w * NFG + f], osr[w], acc);
        out[((size_t)n * OUT_T + (j0 + js)) * NF + g * NFG + f] = acc;
    }
}

// ---------------- launch ----------------
extern "C" void kernel_launch(void* const* d_in, const int* in_sizes, int n_in,
                              void* d_out, int out_size) {
    const float* x  = (const float*)d_in[0];
    const float* cf = (const float*)d_in[1];
    const float* bw = (const float*)d_in[2];
    const float* pw = (const float*)d_in[3];
    float* out = (float*)d_out;

    // dynamic smem sizes (worst-case over supported meta ranges)
    const int conv_smem = (STAGE_FLOATS + 2 * KMAX * NFG + (TT - 1) * CSMAX + KMAX) * 4; // ~92 KB
    const int pool_smem = (PSZ * NFG + NFG * ((POOL_J - 1) * PSTR + PSZ + 1)) * 4;       // ~125 KB

    static int configured = 0;
    if (!configured) {
        cudaFuncSetAttribute(conv_kernel, cudaFuncAttributeMaxDynamicSharedMemorySize, conv_smem);
        cudaFuncSetAttribute(pool_kernel, cudaFuncAttributeMaxDynamicSharedMemorySize, pool_smem);
        configured = 1;
    }

    prep_kernel<<<NG, 256>>>(cf, bw, pw);

    dim3 cgrid((TIME + TT - 1) / TT, BATCH, NG);   // 500 x 32 x 4, early-exit past L1
    conv_kernel<<<cgrid, CONV_THREADS, conv_smem>>>(x);

    dim3 pgrid(OUT_T / POOL_J, BATCH, NG);          // 25 x 32 x 4
    pool_kernel<<<pgrid, POOL_THREADS, pool_smem>>>(out);
}

// round 3
// speedup vs baseline: 1.0020x; 1.0003x over previous
#include <cuda_runtime.h>
#include <math.h>

// ---------------- problem constants ----------------
#define BATCH   32
#define TIME    64000
#define NF      40
#define NG      4
#define NFG     10          // filters per group
#define OUT_T   400
#define PSZ     401         // POOL_SIZE
#define PSTR    160         // POOL_STRIDE
#define KMAX    512         // supported max gabor kernel length (actual <= 451)
#define CSMAX   40          // supported max conv stride (actual ~10)

// conv kernel tiling
#define TT          128     // time points per block
#define TREG        4       // time points per thread
#define CONV_THREADS 160    // 5 filter-pairs x 32 time slots
#define STAGE_STRIDE 133
#define STAGE_FLOATS 1332   // >= 10*133, even (for float2 alignment after)

// pool kernel tiling
#define POOL_J      16
#define POOL_THREADS 320

// ---------------- device scratch ----------------
__device__ float  g_o[(size_t)NG * BATCH * NFG * TIME];   // 327.7 MB squared-modulus conv out
__device__ float2 g_kern[NG * KMAX * NFG];                // gabor taps {cos, sin}
__device__ float  g_win[NG * PSZ * NFG];                  // pooling windows
__device__ int    g_meta[NG][8];                          // cs, k, ws, ps, L1

// ---------------- meta (exact replica of reference numpy logic) ----------------
__device__ __forceinline__ float clip_cf(float v) {
    return fminf(fmaxf(v, 0.0f), 3.14159265358979f);  // rounds to f32(pi)
}
__device__ __forceinline__ float clip_bw(float v) {
    const double Zd = sqrt(1.3862943611198906) / 3.141592653589793; // sqrt(2 ln2)/pi
    return fminf(fmaxf(v, (float)(2.0 * Zd)), (float)(401.0 * Zd));
}
__device__ __forceinline__ float clip_pw(float v) {
    return fminf(fmaxf(v, (float)(2.0 / 401.0)), 0.5f);
}

__device__ __forceinline__ void compute_meta(const float* cf, const float* bw, int g,
                                             int& cs, int& k, int& ws, int& ps, int& L1) {
    float cfmax = -1e30f, bwmax = -1e30f;
#pragma unroll
    for (int f = 0; f < NFG; f++) {
        cfmax = fmaxf(cfmax, clip_cf(cf[g * NFG + f]));
        bwmax = fmaxf(bwmax, clip_bw(bw[g * NFG + f]));
    }
    double s = 3.141592653589793 / (double)cfmax;   // STRIDE_FACTOR = 1
    if (s < 1.0) s = 1.0;
    const int divs[12] = {160, 80, 40, 32, 20, 16, 10, 8, 5, 4, 2, 1};
    cs = 1;
#pragma unroll
    for (int i = 0; i < 12; i++) {
        if ((double)divs[i] <= s) { cs = divs[i]; break; }
    }
    k = (int)((double)bwmax * 3.0);     // truncation like python int()
    if ((k & 1) == 0) k += 1;
    ws = (int)(401.0 / (double)cs + 0.5);
    if ((ws & 1) == 0) ws += 1;
    ps = PSTR / cs;
    L1 = (TIME - 1) / cs + 1;
}

// ---------------- prep: meta + gabor taps + pool windows ----------------
__global__ void prep_kernel(const float* __restrict__ cf, const float* __restrict__ bw,
                            const float* __restrict__ pw) {
    int g = blockIdx.x;
    int tid = threadIdx.x;
    int cs, k, ws, ps, L1;
    compute_meta(cf, bw, g, cs, k, ws, ps, L1);
    if (tid == 0) {
        g_meta[g][0] = cs; g_meta[g][1] = k; g_meta[g][2] = ws;
        g_meta[g][3] = ps; g_meta[g][4] = L1;
    }
    int k2 = k >> 1;
    // gabor taps: norm * {cos,sin}(u'*cf) * exp(-u'^2/(2 bw^2)),  norm = 1/(sqrt(2pi) bw)
    for (int i = tid; i < k * NFG; i += blockDim.x) {
        int u = i / NFG, f = i % NFG;
        float cff = clip_cf(cf[g * NFG + f]);
        float bwf = clip_bw(bw[g * NFG + f]);
        float up = (float)(u - k2);
        float gauss = expf(-(up * up) / (2.0f * bwf * bwf));
        float norm = 1.0f / (sqrtf(2.0f * 3.14159274f) * bwf);
        float sp, cp;
        sincosf(up * cff, &sp, &cp);
        g_kern[g * KMAX * NFG + i] = make_float2(norm * cp * gauss, norm * sp * gauss);
    }
    // pooling windows: exp(-0.5 * ((w - 0.5(ws-1)) / (sigma * 0.5(ws-1)))^2)
    for (int i = tid; i < ws * NFG; i += blockDim.x) {
        int w = i / NFG, f = i % NFG;
        float pwf = clip_pw(pw[g * NFG + f]);
        float sigma = pwf / (float)cs * 401.0f / (float)ws;
        float c = ((float)w - 0.5f * (float)(ws - 1)) / (sigma * 0.5f * (float)(ws - 1));
        g_win[g * PSZ * NFG + i] = expf(-0.5f * c * c);
    }
}

// ---------------- phase 1: gabor conv + squared modulus ----------------
// block: one (g, n, 128-t tile). thread = (filter-pair fg in 0..4, time-slot ts in 0..31),
// each thread accumulates 2 filters x 4 time points (C,S each) -> 16 acc regs.
extern "C" __global__ void __launch_bounds__(CONV_THREADS)
conv_kernel(const float* __restrict__ x) {
    extern __shared__ float smem[];
    int g = blockIdx.z, n = blockIdx.y;
    int cs = g_meta[g][0], k = g_meta[g][1], L1 = g_meta[g][4];
    int t0 = blockIdx.x * TT;
    if (t0 >= L1) return;
    int k2 = k >> 1;

    float* stage = smem;                                   // STAGE_FLOATS
    float2* kern = (float2*)(smem + STAGE_FLOATS);         // k*NFG float2
    float* xs = smem + STAGE_FLOATS + 2 * k * NFG;         // (TT-1)*cs + k floats
    int tid = threadIdx.x;

    // load taps (contiguous) and x tile (zero-padded)
    for (int i = tid; i < k * NFG; i += CONV_THREADS)
        kern[i] = g_kern[g * KMAX * NFG + i];
    long xlo = (long)t0 * cs - k2;
    int xcount = (TT - 1) * cs + k;
    const float* xn = x + (size_t)n * TIME;
    for (int i = tid; i < xcount; i += CONV_THREADS) {
        long xg = xlo + i;
        xs[i] = (xg >= 0 && xg < TIME) ? xn[xg] : 0.0f;
    }
    __syncthreads();

    int fg = tid % 5;
    int ts = tid / 5;          // 0..31
    int f0 = 2 * fg;

    float C0[TREG], S0[TREG], C1[TREG], S1[TREG];
#pragma unroll
    for (int r = 0; r < TREG; r++) { C0[r] = S0[r] = C1[r] = S1[r] = 0.0f; }

    const float* xbase = xs + ts * cs;
    int step = 32 * cs;
#pragma unroll 4
    for (int u = 0; u < k; u++) {
        float2 k0 = kern[u * NFG + f0];
        float2 k1 = kern[u * NFG + f0 + 1];
#pragma unroll
        for (int r = 0; r < TREG; r++) {
            float xv = xbase[r * step + u];
            C0[r] = fmaf(k0.x, xv, C0[r]);
            S0[r] = fmaf(k0.y, xv, S0[r]);
            C1[r] = fmaf(k1.x, xv, C1[r]);
            S1[r] = fmaf(k1.y, xv, S1[r]);
        }
    }

    // stage |.|^2 into smem, then coalesced store
#pragma unroll
    for (int r = 0; r < TREG; r++) {
        int tl = ts + 32 * r;
        stage[f0 * STAGE_STRIDE + tl]       = C0[r] * C0[r] + S0[r] * S0[r];
        stage[(f0 + 1) * STAGE_STRIDE + tl] = C1[r] * C1[r] + S1[r] * S1[r];
    }
    __syncthreads();
    float* obase = g_o + (size_t)(g * BATCH + n) * NFG * TIME;
    for (int i = tid; i < NFG * TT; i += CONV_THREADS) {
        int f = i >> 7, tl = i & (TT - 1);
        int t = t0 + tl;
        if (t < L1) obase[(size_t)f * TIME + t] = stage[f * STAGE_STRIDE + tl];
    }
}

// ---------------- phase 2: gaussian pooling ----------------
// block: one (g, n, 16-frame tile). smem: win[ws][10] + o tile [10][tc] (coalesced load).
extern "C" __global__ void __launch_bounds__(POOL_THREADS)
pool_kernel(float* __restrict__ out) {
    extern __shared__ float smem[];
    int g = blockIdx.z, n = blockIdx.y;
    int cs = g_meta[g][0]; (void)cs;
    int ws = g_meta[g][2], ps = g_meta[g][3], L1 = g_meta[g][4];
    int ws2 = ws >> 1;
    int j0 = blockIdx.x * POOL_J;
    int tc = (POOL_J - 1) * ps + ws;
    int stride = tc + 1;

    float* win = smem;             // ws*NFG
    float* os = smem + ws * NFG;   // NFG*stride
    int tid = threadIdx.x;

    for (int i = tid; i < ws * NFG; i += POOL_THREADS)
        win[i] = g_win[g * PSZ * NFG + i];

    int tbase = j0 * ps - ws2;
    const float* obase = g_o + (size_t)(g * BATCH + n) * NFG * TIME;
    for (int i = tid; i < NFG * tc; i += POOL_THREADS) {
        int f = i / tc, tl = i - f * tc;
        int t = tbase + tl;
        os[f * stride + tl] = (t >= 0 && t < L1) ? obase[(size_t)f * TIME + t] : 0.0f;
    }
    __syncthreads();

    int f = tid % NFG, js = tid / NFG;
    if (js < POOL_J) {
        const float* osr = os + f * stride + js * ps;
        float acc = 0.0f;
#pragma unroll 4
        for (int w = 0; w < ws; w++)
            acc = fmaf(win[w * NFG + f], osr[w], acc);
        out[((size_t)n * OUT_T + (j0 + js)) * NF + g * NFG + f] = acc;
    }
}

// ---------------- launch ----------------
extern "C" void kernel_launch(void* const* d_in, const int* in_sizes, int n_in,
                              void* d_out, int out_size) {
    const float* x  = (const float*)d_in[0];
    const float* cf = (const float*)d_in[1];
    const float* bw = (const float*)d_in[2];
    const float* pw = (const float*)d_in[3];
    float* out = (float*)d_out;

    // dynamic smem sizes (worst-case over supported meta ranges)
    const int conv_smem = (STAGE_FLOATS + 2 * KMAX * NFG + (TT - 1) * CSMAX + KMAX) * 4; // ~92 KB
    const int pool_smem = (PSZ * NFG + NFG * ((POOL_J - 1) * PSTR + PSZ + 1)) * 4;       // ~125 KB

    static int configured = 0;
    if (!configured) {
        cudaFuncSetAttribute(conv_kernel, cudaFuncAttributeMaxDynamicSharedMemorySize, conv_smem);
        cudaFuncSetAttribute(pool_kernel, cudaFuncAttributeMaxDynamicSharedMemorySize, pool_smem);
        configured = 1;
    }

    prep_kernel<<<NG, 256>>>(cf, bw, pw);

    dim3 cgrid((TIME + TT - 1) / TT, BATCH, NG);   // 500 x 32 x 4, early-exit past L1
    conv_kernel<<<cgrid, CONV_THREADS, conv_smem>>>(x);

    dim3 pgrid(OUT_T / POOL_J, BATCH, NG);          // 25 x 32 x 4
    pool_kernel<<<pgrid, POOL_THREADS, pool_smem>>>(out);
}